// round 10
// baseline (speedup 1.0000x reference)
#include <cuda_runtime.h>
#include <cuda_bf16.h>
#include <cstdint>

// ---------------- problem constants ----------------
#define MDIM 4096
#define NDIM 4096
#define KDIM 4096
// zero points: X_ZP = -66, Y_ZP = 160
// (x - zx)(y - zy) summed over K:
//   dot(x,y) - 160*rowsum(x) + 66*colsum(y) + K*zx*zy
#define KZZ (-43253760)          // 4096 * (-66) * 160
#define OUT_SCALE (0.03f * 0.025f)

// ---------------- scratch ----------------
__device__ unsigned char g_xa[(size_t)MDIM * KDIM];   // x packed s8, row-major [M,K]
__device__ unsigned char g_yb[(size_t)NDIM * KDIM];   // y packed u8, K-major [N,K]
__device__ int g_rx[MDIM];                            // rowsum of x, premultiplied by 160
__device__ int g_cyp[32][NDIM];                       // partial colsums of y (one per 128-k slab)

// ---------------- merged conversion kernel ----------------
//  blocks [0, MDIM)          : pack one x row -> s8 + rowsum*160
//  blocks [MDIM, MDIM+4096)  : transpose-pack one 32n x 128k y slab -> u8 [N,K]
//                              + partial colsum (non-atomic, unique cell per block)
__global__ __launch_bounds__(256) void conv_kernel(const int* __restrict__ x,
                                                   const int* __restrict__ y) {
    int b = blockIdx.x;
    int tid = threadIdx.x;
    if (b < MDIM) {
        int row = b;
        const int4* src = reinterpret_cast<const int4*>(x + (size_t)row * KDIM) + tid * 4;
        int sum = 0;
        unsigned int packed[4];
        #pragma unroll
        for (int i = 0; i < 4; i++) {
            int4 v = src[i];
            sum += v.x + v.y + v.z + v.w;
            packed[i] = (v.x & 0xFF) | ((v.y & 0xFF) << 8) | ((v.z & 0xFF) << 16) | ((v.w & 0xFF) << 24);
        }
        uint4 o = make_uint4(packed[0], packed[1], packed[2], packed[3]);
        reinterpret_cast<uint4*>(g_xa + (size_t)row * KDIM)[tid] = o;

        #pragma unroll
        for (int s = 16; s > 0; s >>= 1) sum += __shfl_down_sync(0xFFFFFFFF, sum, s);
        __shared__ int warp_s[8];
        if ((tid & 31) == 0) warp_s[tid >> 5] = sum;
        __syncthreads();
        if (tid == 0) {
            int t = 0;
            #pragma unroll
            for (int w = 0; w < 8; w++) t += warp_s[w];
            g_rx[row] = t * 160;
        }
    } else {
        int t0 = b - MDIM;               // 0..4095
        int seg = t0 >> 7;               // 0..31 (k slab of 128)
        int n0 = (t0 & 127) * 32;
        int k0 = seg * 128;
        int tx = tid & 31;
        int ty = tid >> 5;
        __shared__ unsigned int sh32[32][33];
        __shared__ int red[8][32];
        unsigned char* shb = reinterpret_cast<unsigned char*>(sh32);
        int csum = 0;
        #pragma unroll
        for (int r = 0; r < 16; r++) {
            int kk = ty + r * 8;
            int v = y[(size_t)(k0 + kk) * NDIM + n0 + tx];
            csum += v;
            shb[tx * 132 + kk] = (unsigned char)v;
        }
        red[ty][tx] = csum;
        __syncthreads();
        int n = tid >> 3;
        int wq = tid & 7;
        uint4 o;
        o.x = sh32[n][wq * 4 + 0];
        o.y = sh32[n][wq * 4 + 1];
        o.z = sh32[n][wq * 4 + 2];
        o.w = sh32[n][wq * 4 + 3];
        *reinterpret_cast<uint4*>(&g_yb[(size_t)(n0 + n) * KDIM + k0 + wq * 16]) = o;
        if (ty == 0) {
            int s = 0;
            #pragma unroll
            for (int w = 0; w < 8; w++) s += red[w][tx];
            g_cyp[seg][n0 + tx] = s;      // unique (seg, n) per block: no atomic
        }
    }
}

// ---------------- GEMM (s8 x u8 -> s32 via mma.sync) — proven R8 config ----------------
static constexpr int BM = 128;
static constexpr int BN = 128;
static constexpr int BKB = 128;                  // k bytes per chunk
static constexpr int NCHUNK = KDIM / BKB;        // 32
static constexpr int STAGES = 3;
static constexpr int TILE_BYTES = BM * BKB;      // 16384 (A), same for B
static constexpr int STAGE_BYTES = 2 * TILE_BYTES;   // 32768
static constexpr int CORR_OFF = STAGES * STAGE_BYTES;        // 98304: sRX[128], sCY[128]
static constexpr int SMEM_TOTAL = CORR_OFF + 1024;           // 99328

__device__ __forceinline__ uint32_t smem_to_u32(const void* p) {
    uint32_t a;
    asm("{ .reg .u64 t; cvta.to.shared.u64 t, %1; cvt.u32.u64 %0, t; }" : "=r"(a) : "l"(p));
    return a;
}

#define LDSM_X4(r0, r1, r2, r3, addr) \
    asm volatile("ldmatrix.sync.aligned.m8n8.x4.shared.b16 {%0,%1,%2,%3}, [%4];" \
        : "=r"(r0), "=r"(r1), "=r"(r2), "=r"(r3) : "r"(addr))

#define MMA_S8U8(d, a, b0, b1) \
    asm volatile("mma.sync.aligned.m16n8k32.row.col.s32.s8.u8.s32 " \
        "{%0,%1,%2,%3}, {%4,%5,%6,%7}, {%8,%9}, {%0,%1,%2,%3};" \
        : "+r"((d)[0]), "+r"((d)[1]), "+r"((d)[2]), "+r"((d)[3]) \
        : "r"((a)[0]), "r"((a)[1]), "r"((a)[2]), "r"((a)[3]), "r"(b0), "r"(b1))

#define CP_ASYNC16(dst, src) \
    asm volatile("cp.async.cg.shared.global [%0], [%1], 16;\n" :: "r"(dst), "l"(src))
#define CP_COMMIT()  asm volatile("cp.async.commit_group;\n" ::: "memory")
#define CP_WAIT1()   asm volatile("cp.async.wait_group 1;\n" ::: "memory")
#define CP_WAIT0()   asm volatile("cp.async.wait_group 0;\n" ::: "memory")

__global__ __launch_bounds__(256, 2) void gemm_s8_kernel(float* __restrict__ out) {
    extern __shared__ __align__(1024) char smem[];
    uint32_t sb = smem_to_u32(smem);
    int tid  = threadIdx.x;
    int wid  = tid >> 5;
    int lane = tid & 31;

    int m0 = blockIdx.y * BM;
    int n0 = blockIdx.x * BN;
    int wm = (wid >> 2) * 64;      // warp M offset (2 rows of warps)
    int wn = (wid & 3) * 32;       // warp N offset (4 cols of warps)

    const char* gA = reinterpret_cast<const char*>(g_xa) + (size_t)m0 * KDIM;
    const char* gB = reinterpret_cast<const char*>(g_yb) + (size_t)n0 * KDIM;

    // stash corrections in smem (published by the first main-loop barrier)
    int* sRX = reinterpret_cast<int*>(smem + CORR_OFF);
    int* sCY = sRX + 128;
    if (tid < 128) {
        sRX[tid] = __ldg(&g_rx[m0 + tid]);                    // already *160
    } else if (tid < 192) {
        int col = n0 + (tid - 128) * 2;
        int s0 = 0, s1 = 0;
        #pragma unroll
        for (int seg = 0; seg < 32; seg++) {
            s0 += __ldg(&g_cyp[seg][col]);
            s1 += __ldg(&g_cyp[seg][col + 1]);
        }
        sCY[(tid - 128) * 2]     = s0 * 66 + KZZ;
        sCY[(tid - 128) * 2 + 1] = s1 * 66 + KZZ;
    }

    // per-thread cp.async geometry: 8 x 16B per stage
    const char* cp_src[8];
    uint32_t cp_dst[8];
    #pragma unroll
    for (int i = 0; i < 8; i++) {
        int idx = tid + i * 256;          // 0..2047
        int which = idx >> 10;            // 0=A, 1=B
        int j = idx & 1023;
        int row = j >> 3;
        int c16 = (j & 7) * 16;
        uint32_t off = (uint32_t)(row * BKB + c16);
        cp_dst[i] = (uint32_t)(which * TILE_BYTES) + (off ^ ((off >> 3) & 0x70));
        cp_src[i] = (which ? gB : gA) + (size_t)row * KDIM + c16;
    }

    // ldmatrix per-thread bases
    int rA = ((lane >> 3) & 1) * 8 + (lane & 7);
    int kA = ((lane >> 4) & 1) * 16;
    uint32_t offA_lin = (uint32_t)((wm + rA) * BKB + kA);
    int rB = ((lane >> 4) & 1) * 8 + (lane & 7);
    int kB = ((lane >> 3) & 1) * 16;
    uint32_t offB_lin = (uint32_t)((wn + rB) * BKB + kB);
    uint32_t xmA = (uint32_t)((rA & 7) << 4);
    uint32_t xmB = (uint32_t)((rB & 7) << 4);

    int d[4][4][4];
    #pragma unroll
    for (int mi = 0; mi < 4; mi++)
        #pragma unroll
        for (int ni = 0; ni < 4; ni++)
            #pragma unroll
            for (int r = 0; r < 4; r++) d[mi][ni][r] = 0;

    auto load_chunk = [&](int c, int s) {
        uint32_t base = sb + (uint32_t)s * STAGE_BYTES;
        size_t koff = (size_t)c * BKB;
        #pragma unroll
        for (int i = 0; i < 8; i++) {
            CP_ASYNC16(base + cp_dst[i], cp_src[i] + koff);
        }
        CP_COMMIT();
    };

    load_chunk(0, 0);
    load_chunk(1, 1);

    #pragma unroll 1
    for (int c = 0; c < NCHUNK; c++) {
        if (c < NCHUNK - 1) CP_WAIT1();
        else                CP_WAIT0();
        __syncthreads();   // publishes chunk c; retires last iter's reads of slot (c+2)%3

        if (c + 2 < NCHUNK) load_chunk(c + 2, (c + 2) % STAGES);

        int s = c % STAGES;
        uint32_t stA = sb + (uint32_t)s * STAGE_BYTES;
        uint32_t stB = stA + TILE_BYTES;

        #pragma unroll
        for (int ks = 0; ks < 4; ks++) {
            uint32_t a[4][4];
            #pragma unroll
            for (int mi = 0; mi < 4; mi++) {
                uint32_t addr = stA + ((offA_lin + (uint32_t)(mi * 2048 + ks * 32)) ^ xmA);
                LDSM_X4(a[mi][0], a[mi][1], a[mi][2], a[mi][3], addr);
            }
            uint32_t b[4][2];
            #pragma unroll
            for (int j2 = 0; j2 < 2; j2++) {
                uint32_t addr = stB + ((offB_lin + (uint32_t)(j2 * 2048 + ks * 32)) ^ xmB);
                LDSM_X4(b[2 * j2][0], b[2 * j2][1], b[2 * j2 + 1][0], b[2 * j2 + 1][1], addr);
            }
            #pragma unroll
            for (int mi = 0; mi < 4; mi++)
                #pragma unroll
                for (int ni = 0; ni < 4; ni++)
                    MMA_S8U8(d[mi][ni], a[mi], b[ni][0], b[ni][1]);
        }
    }

    // ---------------- epilogue: zero-point correction + scale (smem-fed) ----------------
    const float S = OUT_SCALE;
    int rlo = lane >> 2;
    int cc  = (lane & 3) * 2;
    #pragma unroll
    for (int mi = 0; mi < 4; mi++) {
        int lrow = wm + mi * 16 + rlo;
        int row0 = m0 + lrow;
        int rxa = sRX[lrow];
        int rxb = sRX[lrow + 8];
        #pragma unroll
        for (int ni = 0; ni < 4; ni++) {
            int lcol = wn + ni * 8 + cc;
            int col = n0 + lcol;
            int cy0 = sCY[lcol];
            int cy1 = sCY[lcol + 1];
            const int* dd = d[mi][ni];
            float2 v0, v1;
            v0.x = S * (float)(dd[0] - rxa + cy0);
            v0.y = S * (float)(dd[1] - rxa + cy1);
            v1.x = S * (float)(dd[2] - rxb + cy0);
            v1.y = S * (float)(dd[3] - rxb + cy1);
            *reinterpret_cast<float2*>(out + (size_t)row0 * NDIM + col) = v0;
            *reinterpret_cast<float2*>(out + (size_t)(row0 + 8) * NDIM + col) = v1;
        }
    }
}

// ---------------- launch ----------------
extern "C" void kernel_launch(void* const* d_in, const int* in_sizes, int n_in,
                              void* d_out, int out_size) {
    const int* x = (const int*)d_in[0];   // [M, K] int32 (int8-range)
    const int* y = (const int*)d_in[1];   // [K, N] int32 (uint8-range)
    float* out = (float*)d_out;

    conv_kernel<<<MDIM + 4096, 256>>>(x, y);

    cudaFuncSetAttribute(gemm_s8_kernel, cudaFuncAttributeMaxDynamicSharedMemorySize, SMEM_TOTAL);
    gemm_s8_kernel<<<dim3(NDIM / BN, MDIM / BM), 256, SMEM_TOTAL>>>(out);
}

// round 11
// speedup vs baseline: 1.6322x; 1.6322x over previous
#include <cuda_runtime.h>
#include <cuda_bf16.h>
#include <cstdint>

// ---------------- problem constants ----------------
#define MDIM 4096
#define NDIM 4096
#define KDIM 4096
// zero points: X_ZP = -66, Y_ZP = 160
// (x - zx)(y - zy) summed over K:
//   dot(x,y) - 160*rowsum(x) + 66*colsum(y) + K*zx*zy
#define KZZ (-43253760)          // 4096 * (-66) * 160
#define OUT_SCALE (0.03f * 0.025f)

// ---------------- scratch ----------------
__device__ unsigned char g_xa[(size_t)MDIM * KDIM];   // x packed s8, row-major [M,K]
__device__ unsigned char g_yb[(size_t)NDIM * KDIM];   // y packed u8, K-major [N,K]
__device__ int g_rx[MDIM];                            // rowsum of x, premultiplied by 160
__device__ int g_cy[NDIM];                            // colsum of y

// ---------------- merged conversion kernel ----------------
//  blocks [0, MDIM)          : pack one x row -> s8 + rowsum*160
//  blocks [MDIM, MDIM+4096)  : transpose-pack one 32n x 128k y slab -> u8 [N,K] + colsum atomics
__global__ __launch_bounds__(256) void conv_kernel(const int* __restrict__ x,
                                                   const int* __restrict__ y) {
    int b = blockIdx.x;
    int tid = threadIdx.x;
    if (b < MDIM) {
        // ---- x path: one block per row ----
        int row = b;
        const int4* src = reinterpret_cast<const int4*>(x + (size_t)row * KDIM) + tid * 4;
        int sum = 0;
        unsigned int packed[4];
        #pragma unroll
        for (int i = 0; i < 4; i++) {
            int4 v = src[i];
            sum += v.x + v.y + v.z + v.w;
            packed[i] = (v.x & 0xFF) | ((v.y & 0xFF) << 8) | ((v.z & 0xFF) << 16) | ((v.w & 0xFF) << 24);
        }
        uint4 o = make_uint4(packed[0], packed[1], packed[2], packed[3]);
        reinterpret_cast<uint4*>(g_xa + (size_t)row * KDIM)[tid] = o;

        #pragma unroll
        for (int s = 16; s > 0; s >>= 1) sum += __shfl_down_sync(0xFFFFFFFF, sum, s);
        __shared__ int warp_s[8];
        if ((tid & 31) == 0) warp_s[tid >> 5] = sum;
        __syncthreads();
        if (tid == 0) {
            int t = 0;
            #pragma unroll
            for (int w = 0; w < 8; w++) t += warp_s[w];
            g_rx[row] = t * 160;   // fold zero-point multiplier
        }
    } else {
        // ---- y path: one block per 32n x 128k slab ----
        int t0 = b - MDIM;               // 0..4095
        int n0 = (t0 & 127) * 32;
        int k0 = (t0 >> 7) * 128;
        int tx = tid & 31;               // n within strip
        int ty = tid >> 5;               // 0..7 (one per warp)
        // sh words: [n][33] uint32 per row = 132 bytes of k data (128 used)
        __shared__ unsigned int sh32[32][33];
        __shared__ int red[8][32];
        unsigned char* shb = reinterpret_cast<unsigned char*>(sh32);
        int csum = 0;
        #pragma unroll
        for (int r = 0; r < 16; r++) {
            int kk = ty + r * 8;         // 0..127
            int v = y[(size_t)(k0 + kk) * NDIM + n0 + tx];
            csum += v;
            shb[tx * 132 + kk] = (unsigned char)v;
        }
        red[ty][tx] = csum;
        __syncthreads();
        // write: 256 threads, each emits 16 consecutive k bytes of one n row
        int n = tid >> 3;                // 0..31
        int wq = tid & 7;                // 16B segment within the 128B row
        uint4 o;
        o.x = sh32[n][wq * 4 + 0];
        o.y = sh32[n][wq * 4 + 1];
        o.z = sh32[n][wq * 4 + 2];
        o.w = sh32[n][wq * 4 + 3];
        *reinterpret_cast<uint4*>(&g_yb[(size_t)(n0 + n) * KDIM + k0 + wq * 16]) = o;
        if (ty == 0) {
            int s = 0;
            #pragma unroll
            for (int w = 0; w < 8; w++) s += red[w][tx];
            atomicAdd(&g_cy[n0 + tx], s);
        }
    }
}

// ---------------- GEMM (s8 x u8 -> s32 via mma.sync) ----------------
static constexpr int BM = 128;
static constexpr int BN = 128;
static constexpr int BKB = 128;                  // k bytes per chunk
static constexpr int NCHUNK = KDIM / BKB;        // 32
static constexpr int STAGES = 3;
static constexpr int TILE_BYTES = BM * BKB;      // 16384 (A), same for B
static constexpr int STAGE_BYTES = 2 * TILE_BYTES;   // 32768
static constexpr int CORR_OFF = STAGES * STAGE_BYTES;        // 98304: sRX[128], sCY[128]
static constexpr int SMEM_TOTAL = CORR_OFF + 1024;           // 99328

__device__ __forceinline__ uint32_t smem_to_u32(const void* p) {
    uint32_t a;
    asm("{ .reg .u64 t; cvta.to.shared.u64 t, %1; cvt.u32.u64 %0, t; }" : "=r"(a) : "l"(p));
    return a;
}

#define LDSM_X4(r0, r1, r2, r3, addr) \
    asm volatile("ldmatrix.sync.aligned.m8n8.x4.shared.b16 {%0,%1,%2,%3}, [%4];" \
        : "=r"(r0), "=r"(r1), "=r"(r2), "=r"(r3) : "r"(addr))

#define MMA_S8U8(d, a, b0, b1) \
    asm volatile("mma.sync.aligned.m16n8k32.row.col.s32.s8.u8.s32 " \
        "{%0,%1,%2,%3}, {%4,%5,%6,%7}, {%8,%9}, {%0,%1,%2,%3};" \
        : "+r"((d)[0]), "+r"((d)[1]), "+r"((d)[2]), "+r"((d)[3]) \
        : "r"((a)[0]), "r"((a)[1]), "r"((a)[2]), "r"((a)[3]), "r"(b0), "r"(b1))

#define CP_ASYNC16(dst, src) \
    asm volatile("cp.async.cg.shared.global [%0], [%1], 16;\n" :: "r"(dst), "l"(src))
#define CP_COMMIT()  asm volatile("cp.async.commit_group;\n" ::: "memory")
#define CP_WAIT1()   asm volatile("cp.async.wait_group 1;\n" ::: "memory")
#define CP_WAIT0()   asm volatile("cp.async.wait_group 0;\n" ::: "memory")

__global__ __launch_bounds__(256, 2) void gemm_s8_kernel(float* __restrict__ out) {
    extern __shared__ __align__(1024) char smem[];
    uint32_t sb = smem_to_u32(smem);
    int tid  = threadIdx.x;
    int wid  = tid >> 5;
    int lane = tid & 31;

    int m0 = blockIdx.y * BM;
    int n0 = blockIdx.x * BN;
    int wm = (wid >> 2) * 64;      // warp M offset (2 rows of warps)
    int wn = (wid & 3) * 32;       // warp N offset (4 cols of warps)

    const char* gA = reinterpret_cast<const char*>(g_xa) + (size_t)m0 * KDIM;
    const char* gB = reinterpret_cast<const char*>(g_yb) + (size_t)n0 * KDIM;

    // stash corrections in smem (published by the first main-loop barrier)
    int* sRX = reinterpret_cast<int*>(smem + CORR_OFF);
    int* sCY = sRX + 128;
    if (tid < 128) {
        sRX[tid] = __ldg(&g_rx[m0 + tid]);                    // already *160
    } else {
        sCY[tid - 128] = __ldg(&g_cy[n0 + (tid - 128)]) * 66 + KZZ;  // fold here
    }

    // per-thread cp.async geometry: 8 x 16B per stage
    const char* cp_src[8];
    uint32_t cp_dst[8];
    #pragma unroll
    for (int i = 0; i < 8; i++) {
        int idx = tid + i * 256;          // 0..2047
        int which = idx >> 10;            // 0=A, 1=B
        int j = idx & 1023;
        int row = j >> 3;
        int c16 = (j & 7) * 16;
        uint32_t off = (uint32_t)(row * BKB + c16);
        cp_dst[i] = (uint32_t)(which * TILE_BYTES) + (off ^ ((off >> 3) & 0x70));
        cp_src[i] = (which ? gB : gA) + (size_t)row * KDIM + c16;
    }

    // ldmatrix per-thread bases
    int rA = ((lane >> 3) & 1) * 8 + (lane & 7);
    int kA = ((lane >> 4) & 1) * 16;
    uint32_t offA_lin = (uint32_t)((wm + rA) * BKB + kA);
    int rB = ((lane >> 4) & 1) * 8 + (lane & 7);
    int kB = ((lane >> 3) & 1) * 16;
    uint32_t offB_lin = (uint32_t)((wn + rB) * BKB + kB);
    uint32_t xmA = (uint32_t)((rA & 7) << 4);
    uint32_t xmB = (uint32_t)((rB & 7) << 4);

    int d[4][4][4];
    #pragma unroll
    for (int mi = 0; mi < 4; mi++)
        #pragma unroll
        for (int ni = 0; ni < 4; ni++)
            #pragma unroll
            for (int r = 0; r < 4; r++) d[mi][ni][r] = 0;

    auto load_chunk = [&](int c, int s) {
        uint32_t base = sb + (uint32_t)s * STAGE_BYTES;
        size_t koff = (size_t)c * BKB;
        #pragma unroll
        for (int i = 0; i < 8; i++) {
            CP_ASYNC16(base + cp_dst[i], cp_src[i] + koff);
        }
        CP_COMMIT();
    };

    load_chunk(0, 0);
    load_chunk(1, 1);

    #pragma unroll 1
    for (int c = 0; c < NCHUNK; c++) {
        if (c < NCHUNK - 1) CP_WAIT1();
        else                CP_WAIT0();
        __syncthreads();   // publishes chunk c; retires last iter's reads of slot (c+2)%3

        if (c + 2 < NCHUNK) load_chunk(c + 2, (c + 2) % STAGES);

        int s = c % STAGES;
        uint32_t stA = sb + (uint32_t)s * STAGE_BYTES;
        uint32_t stB = stA + TILE_BYTES;

        #pragma unroll
        for (int ks = 0; ks < 4; ks++) {
            uint32_t a[4][4];
            #pragma unroll
            for (int mi = 0; mi < 4; mi++) {
                uint32_t addr = stA + ((offA_lin + (uint32_t)(mi * 2048 + ks * 32)) ^ xmA);
                LDSM_X4(a[mi][0], a[mi][1], a[mi][2], a[mi][3], addr);
            }
            uint32_t b[4][2];
            #pragma unroll
            for (int j2 = 0; j2 < 2; j2++) {
                uint32_t addr = stB + ((offB_lin + (uint32_t)(j2 * 2048 + ks * 32)) ^ xmB);
                LDSM_X4(b[2 * j2][0], b[2 * j2][1], b[2 * j2 + 1][0], b[2 * j2 + 1][1], addr);
            }
            #pragma unroll
            for (int mi = 0; mi < 4; mi++)
                #pragma unroll
                for (int ni = 0; ni < 4; ni++)
                    MMA_S8U8(d[mi][ni], a[mi], b[ni][0], b[ni][1]);
        }
    }

    // ---------------- epilogue: zero-point correction + scale (smem-fed) ----------------
    const float S = OUT_SCALE;
    int rlo = lane >> 2;
    int cc  = (lane & 3) * 2;
    #pragma unroll
    for (int mi = 0; mi < 4; mi++) {
        int lrow = wm + mi * 16 + rlo;
        int row0 = m0 + lrow;
        int rxa = sRX[lrow];
        int rxb = sRX[lrow + 8];
        #pragma unroll
        for (int ni = 0; ni < 4; ni++) {
            int lcol = wn + ni * 8 + cc;
            int col = n0 + lcol;
            int cy0 = sCY[lcol];
            int cy1 = sCY[lcol + 1];
            const int* dd = d[mi][ni];
            float2 v0, v1;
            v0.x = S * (float)(dd[0] - rxa + cy0);
            v0.y = S * (float)(dd[1] - rxa + cy1);
            v1.x = S * (float)(dd[2] - rxb + cy0);
            v1.y = S * (float)(dd[3] - rxb + cy1);
            *reinterpret_cast<float2*>(out + (size_t)row0 * NDIM + col) = v0;
            *reinterpret_cast<float2*>(out + (size_t)(row0 + 8) * NDIM + col) = v1;
        }
    }
}

// ---------------- launch ----------------
extern "C" void kernel_launch(void* const* d_in, const int* in_sizes, int n_in,
                              void* d_out, int out_size) {
    const int* x = (const int*)d_in[0];   // [M, K] int32 (int8-range)
    const int* y = (const int*)d_in[1];   // [K, N] int32 (uint8-range)
    float* out = (float*)d_out;

    // zero g_cy via a memset node (no allocation)
    void* cy_ptr = nullptr;
    cudaGetSymbolAddress(&cy_ptr, g_cy);
    cudaMemsetAsync(cy_ptr, 0, NDIM * sizeof(int), 0);

    conv_kernel<<<MDIM + 4096, 256>>>(x, y);

    cudaFuncSetAttribute(gemm_s8_kernel, cudaFuncAttributeMaxDynamicSharedMemorySize, SMEM_TOTAL);
    gemm_s8_kernel<<<dim3(NDIM / BN, MDIM / BM), 256, SMEM_TOTAL>>>(out);
}

// round 13
// speedup vs baseline: 1.6532x; 1.0129x over previous
#include <cuda_runtime.h>
#include <cuda_bf16.h>
#include <cstdint>

// ---------------- problem constants ----------------
#define MDIM 4096
#define NDIM 4096
#define KDIM 4096
// zero points: X_ZP = -66, Y_ZP = 160
// (x - zx)(y - zy) summed over K:
//   dot(x,y) - 160*rowsum(x) + 66*colsum(y) + K*zx*zy
#define KZZ (-43253760)          // 4096 * (-66) * 160
#define OUT_SCALE (0.03f * 0.025f)

// ---------------- scratch ----------------
__device__ unsigned char g_xa[(size_t)MDIM * KDIM];   // x packed s8, row-major [M,K]
__device__ unsigned char g_yb[(size_t)NDIM * KDIM];   // y packed u8, K-major [N,K]
__device__ int g_rx[MDIM];                            // rowsum of x, premultiplied by 160
__device__ int g_cy[NDIM];                            // colsum of y

// ---------------- merged conversion kernel (proven config) ----------------
__global__ __launch_bounds__(256) void conv_kernel(const int* __restrict__ x,
                                                   const int* __restrict__ y) {
    int b = blockIdx.x;
    int tid = threadIdx.x;
    if (b < MDIM) {
        int row = b;
        const int4* src = reinterpret_cast<const int4*>(x + (size_t)row * KDIM) + tid * 4;
        int sum = 0;
        unsigned int packed[4];
        #pragma unroll
        for (int i = 0; i < 4; i++) {
            int4 v = src[i];
            sum += v.x + v.y + v.z + v.w;
            packed[i] = (v.x & 0xFF) | ((v.y & 0xFF) << 8) | ((v.z & 0xFF) << 16) | ((v.w & 0xFF) << 24);
        }
        uint4 o = make_uint4(packed[0], packed[1], packed[2], packed[3]);
        reinterpret_cast<uint4*>(g_xa + (size_t)row * KDIM)[tid] = o;

        #pragma unroll
        for (int s = 16; s > 0; s >>= 1) sum += __shfl_down_sync(0xFFFFFFFF, sum, s);
        __shared__ int warp_s[8];
        if ((tid & 31) == 0) warp_s[tid >> 5] = sum;
        __syncthreads();
        if (tid == 0) {
            int t = 0;
            #pragma unroll
            for (int w = 0; w < 8; w++) t += warp_s[w];
            g_rx[row] = t * 160;
        }
    } else {
        int t0 = b - MDIM;               // 0..4095
        int n0 = (t0 & 127) * 32;
        int k0 = (t0 >> 7) * 128;
        int tx = tid & 31;
        int ty = tid >> 5;
        __shared__ unsigned int sh32[32][33];
        __shared__ int red[8][32];
        unsigned char* shb = reinterpret_cast<unsigned char*>(sh32);
        int csum = 0;
        #pragma unroll
        for (int r = 0; r < 16; r++) {
            int kk = ty + r * 8;
            int v = y[(size_t)(k0 + kk) * NDIM + n0 + tx];
            csum += v;
            shb[tx * 132 + kk] = (unsigned char)v;
        }
        red[ty][tx] = csum;
        __syncthreads();
        int n = tid >> 3;
        int wq = tid & 7;
        uint4 o;
        o.x = sh32[n][wq * 4 + 0];
        o.y = sh32[n][wq * 4 + 1];
        o.z = sh32[n][wq * 4 + 2];
        o.w = sh32[n][wq * 4 + 3];
        *reinterpret_cast<uint4*>(&g_yb[(size_t)(n0 + n) * KDIM + k0 + wq * 16]) = o;
        if (ty == 0) {
            int s = 0;
            #pragma unroll
            for (int w = 0; w < 8; w++) s += red[w][tx];
            atomicAdd(&g_cy[n0 + tx], s);
        }
    }
}

// ---------------- GEMM (s8 x u8 -> s32 via mma.sync, mbarrier pipeline) ----------------
static constexpr int BM = 128;
static constexpr int BN = 128;
static constexpr int BKB = 128;                  // k bytes per chunk
static constexpr int NCHUNK = KDIM / BKB;        // 32
static constexpr int STAGES = 3;
static constexpr int TILE_BYTES = BM * BKB;      // 16384 (A), same for B
static constexpr int STAGE_BYTES = 2 * TILE_BYTES;   // 32768
static constexpr int CORR_OFF = STAGES * STAGE_BYTES;        // 98304: sRX[128], sCY[128]
static constexpr int MBAR_OFF = CORR_OFF + 1024;             // full[3], empty[3] mbarriers
static constexpr int SMEM_TOTAL = MBAR_OFF + 64;             // 99392

__device__ __forceinline__ uint32_t smem_to_u32(const void* p) {
    uint32_t a;
    asm("{ .reg .u64 t; cvta.to.shared.u64 t, %1; cvt.u32.u64 %0, t; }" : "=r"(a) : "l"(p));
    return a;
}

#define LDSM_X4(r0, r1, r2, r3, addr) \
    asm volatile("ldmatrix.sync.aligned.m8n8.x4.shared.b16 {%0,%1,%2,%3}, [%4];" \
        : "=r"(r0), "=r"(r1), "=r"(r2), "=r"(r3) : "r"(addr))

#define MMA_S8U8(d, a, b0, b1) \
    asm volatile("mma.sync.aligned.m16n8k32.row.col.s32.s8.u8.s32 " \
        "{%0,%1,%2,%3}, {%4,%5,%6,%7}, {%8,%9}, {%0,%1,%2,%3};" \
        : "+r"((d)[0]), "+r"((d)[1]), "+r"((d)[2]), "+r"((d)[3]) \
        : "r"((a)[0]), "r"((a)[1]), "r"((a)[2]), "r"((a)[3]), "r"(b0), "r"(b1))

#define CP_ASYNC16(dst, src) \
    asm volatile("cp.async.cg.shared.global [%0], [%1], 16;\n" :: "r"(dst), "l"(src))

#define MBAR_INIT(addr, cnt) \
    asm volatile("mbarrier.init.shared.b64 [%0], %1;" :: "r"(addr), "r"(cnt) : "memory")
#define MBAR_ARRIVE(addr) \
    asm volatile("mbarrier.arrive.shared.b64 _, [%0];" :: "r"(addr) : "memory")
#define CP_MBAR_NOINC(addr) \
    asm volatile("cp.async.mbarrier.arrive.noinc.shared.b64 [%0];" :: "r"(addr) : "memory")
#define MBAR_WAIT(addr, parity) do { \
    uint32_t _m = (addr); uint32_t _p = (parity); uint32_t _ok; \
    asm volatile("{\n\t.reg .pred p;\n\t" \
        "mbarrier.try_wait.parity.acquire.cta.shared::cta.b64 p, [%1], %2;\n\t" \
        "selp.b32 %0, 1, 0, p;\n\t}" : "=r"(_ok) : "r"(_m), "r"(_p) : "memory"); \
    if (!_ok) { \
        asm volatile("{\n\t.reg .pred P1;\n\t" \
            "WL_%=:\n\t" \
            "mbarrier.try_wait.parity.acquire.cta.shared::cta.b64 P1, [%0], %1, 0x989680;\n\t" \
            "@P1 bra.uni WD_%=;\n\t" \
            "bra.uni WL_%=;\n\t" \
            "WD_%=:\n\t}" :: "r"(_m), "r"(_p) : "memory"); \
    } \
} while (0)

__global__ __launch_bounds__(256, 2) void gemm_s8_kernel(float* __restrict__ out) {
    extern __shared__ __align__(1024) char smem[];
    uint32_t sb = smem_to_u32(smem);
    int tid  = threadIdx.x;
    int wid  = tid >> 5;
    int lane = tid & 31;

    int m0 = blockIdx.y * BM;
    int n0 = blockIdx.x * BN;
    int wm = (wid >> 2) * 64;      // warp M offset (2 rows of warps)
    int wn = (wid & 3) * 32;       // warp N offset (4 cols of warps)

    const char* gA = reinterpret_cast<const char*>(g_xa) + (size_t)m0 * KDIM;
    const char* gB = reinterpret_cast<const char*>(g_yb) + (size_t)n0 * KDIM;

    // mbarriers: full[s] at MBAR_OFF + 8s, empty[s] at MBAR_OFF + 24 + 8s
    uint32_t mb_full  = sb + MBAR_OFF;
    uint32_t mb_empty = sb + MBAR_OFF + 24;
    if (tid == 0) {
        #pragma unroll
        for (int s = 0; s < STAGES; s++) {
            MBAR_INIT(mb_full + 8 * s, 256);
            MBAR_INIT(mb_empty + 8 * s, 256);
        }
    }

    // stash corrections in smem (published by the syncthreads below)
    int* sRX = reinterpret_cast<int*>(smem + CORR_OFF);
    int* sCY = sRX + 128;
    if (tid < 128) {
        sRX[tid] = __ldg(&g_rx[m0 + tid]);                    // already *160
    } else {
        sCY[tid - 128] = __ldg(&g_cy[n0 + (tid - 128)]) * 66 + KZZ;
    }

    // per-thread cp.async geometry: 8 x 16B per stage
    const char* cp_src[8];
    uint32_t cp_dst[8];
    #pragma unroll
    for (int i = 0; i < 8; i++) {
        int idx = tid + i * 256;          // 0..2047
        int which = idx >> 10;            // 0=A, 1=B
        int j = idx & 1023;
        int row = j >> 3;
        int c16 = (j & 7) * 16;
        uint32_t off = (uint32_t)(row * BKB + c16);
        cp_dst[i] = (uint32_t)(which * TILE_BYTES) + (off ^ ((off >> 3) & 0x70));
        cp_src[i] = (which ? gB : gA) + (size_t)row * KDIM + c16;
    }

    // ldmatrix per-thread bases
    int rA = ((lane >> 3) & 1) * 8 + (lane & 7);
    int kA = ((lane >> 4) & 1) * 16;
    uint32_t offA_lin = (uint32_t)((wm + rA) * BKB + kA);
    int rB = ((lane >> 4) & 1) * 8 + (lane & 7);
    int kB = ((lane >> 3) & 1) * 16;
    uint32_t offB_lin = (uint32_t)((wn + rB) * BKB + kB);
    uint32_t xmA = (uint32_t)((rA & 7) << 4);
    uint32_t xmB = (uint32_t)((rB & 7) << 4);

    int d[4][4][4];
    #pragma unroll
    for (int mi = 0; mi < 4; mi++)
        #pragma unroll
        for (int ni = 0; ni < 4; ni++)
            #pragma unroll
            for (int r = 0; r < 4; r++) d[mi][ni][r] = 0;

    auto load_chunk = [&](int c, int s) {
        uint32_t base = sb + (uint32_t)s * STAGE_BYTES;
        size_t koff = (size_t)c * BKB;
        #pragma unroll
        for (int i = 0; i < 8; i++) {
            CP_ASYNC16(base + cp_dst[i], cp_src[i] + koff);
        }
        CP_MBAR_NOINC(mb_full + 8 * s);
    };

    __syncthreads();   // mbarrier init + sRX/sCY visible to all

    load_chunk(0, 0);
    load_chunk(1, 1);

    // pipeline state: consumer slot/parity, producer slot/parity
    int cs = 0, cpar = 0;          // consumer: slot of chunk c, parity (c/3)&1
    int ps = 2;                    // producer target slot for chunk c+2 (c=0 -> slot 2)
    int ppar = 1;                  // flips to 0 at first wrap (t=3 -> slot 0)

    #pragma unroll 1
    for (int c = 0; c < NCHUNK; c++) {
        MBAR_WAIT(mb_full + 8 * cs, cpar);

        uint32_t stA = sb + (uint32_t)cs * STAGE_BYTES;
        uint32_t stB = stA + TILE_BYTES;

        #pragma unroll
        for (int ks = 0; ks < 4; ks++) {
            uint32_t a[4][4];
            #pragma unroll
            for (int mi = 0; mi < 4; mi++) {
                uint32_t addr = stA + ((offA_lin + (uint32_t)(mi * 2048 + ks * 32)) ^ xmA);
                LDSM_X4(a[mi][0], a[mi][1], a[mi][2], a[mi][3], addr);
            }
            uint32_t b[4][2];
            #pragma unroll
            for (int j2 = 0; j2 < 2; j2++) {
                uint32_t addr = stB + ((offB_lin + (uint32_t)(j2 * 2048 + ks * 32)) ^ xmB);
                LDSM_X4(b[2 * j2][0], b[2 * j2][1], b[2 * j2 + 1][0], b[2 * j2 + 1][1], addr);
            }
            #pragma unroll
            for (int mi = 0; mi < 4; mi++)
                #pragma unroll
                for (int ni = 0; ni < 4; ni++)
                    MMA_S8U8(d[mi][ni], a[mi], b[ni][0], b[ni][1]);
        }

        // done reading slot cs (fragments consumed by MMAs above)
        MBAR_ARRIVE(mb_empty + 8 * cs);

        // prefetch chunk c+2 into slot ps
        int t = c + 2;
        if (t < NCHUNK) {
            if (ps == 0) ppar ^= 1;          // slot wrapped: next empty-completion parity
            if (t >= STAGES) MBAR_WAIT(mb_empty + 8 * ps, ppar);
            load_chunk(t, ps);
            ps = (ps == 2) ? 0 : ps + 1;
        }

        cs = (cs == 2) ? 0 : cs + 1;
        if (cs == 0) cpar ^= 1;
    }

    // ---------------- epilogue: zero-point correction + scale (smem-fed) ----------------
    const float S = OUT_SCALE;
    int rlo = lane >> 2;
    int cc  = (lane & 3) * 2;
    #pragma unroll
    for (int mi = 0; mi < 4; mi++) {
        int lrow = wm + mi * 16 + rlo;
        int row0 = m0 + lrow;
        int rxa = sRX[lrow];
        int rxb = sRX[lrow + 8];
        #pragma unroll
        for (int ni = 0; ni < 4; ni++) {
            int lcol = wn + ni * 8 + cc;
            int col = n0 + lcol;
            int cy0 = sCY[lcol];
            int cy1 = sCY[lcol + 1];
            const int* dd = d[mi][ni];
            float2 v0, v1;
            v0.x = S * (float)(dd[0] - rxa + cy0);
            v0.y = S * (float)(dd[1] - rxa + cy1);
            v1.x = S * (float)(dd[2] - rxb + cy0);
            v1.y = S * (float)(dd[3] - rxb + cy1);
            *reinterpret_cast<float2*>(out + (size_t)row0 * NDIM + col) = v0;
            *reinterpret_cast<float2*>(out + (size_t)(row0 + 8) * NDIM + col) = v1;
        }
    }
}

// ---------------- launch ----------------
extern "C" void kernel_launch(void* const* d_in, const int* in_sizes, int n_in,
                              void* d_out, int out_size) {
    const int* x = (const int*)d_in[0];   // [M, K] int32 (int8-range)
    const int* y = (const int*)d_in[1];   // [K, N] int32 (uint8-range)
    float* out = (float*)d_out;

    // zero g_cy via a memset node (no allocation)
    void* cy_ptr = nullptr;
    cudaGetSymbolAddress(&cy_ptr, g_cy);
    cudaMemsetAsync(cy_ptr, 0, NDIM * sizeof(int), 0);

    conv_kernel<<<MDIM + 4096, 256>>>(x, y);

    cudaFuncSetAttribute(gemm_s8_kernel, cudaFuncAttributeMaxDynamicSharedMemorySize, SMEM_TOTAL);
    gemm_s8_kernel<<<dim3(NDIM / BN, MDIM / BM), 256, SMEM_TOTAL>>>(out);
}

// round 15
// speedup vs baseline: 1.7595x; 1.0643x over previous
#include <cuda_runtime.h>
#include <cuda_bf16.h>
#include <cstdint>

// ---------------- problem constants ----------------
#define MDIM 4096
#define NDIM 4096
#define KDIM 4096
#define KZZ (-43253760)          // 4096 * (-66) * 160
#define OUT_SCALE (0.03f * 0.025f)

// ---------------- scratch ----------------
__device__ unsigned char g_xa[(size_t)MDIM * KDIM];   // x packed s8, row-major [M,K]
__device__ unsigned char g_yb[(size_t)NDIM * KDIM];   // y packed u8, K-major [N,K]
__device__ int g_rx[MDIM];                            // rowsum of x, premultiplied by 160
__device__ int g_cy[NDIM];                            // colsum of y

// ---------------- merged conversion kernel (proven config) ----------------
__global__ __launch_bounds__(256) void conv_kernel(const int* __restrict__ x,
                                                   const int* __restrict__ y) {
    int b = blockIdx.x;
    int tid = threadIdx.x;
    if (b < MDIM) {
        int row = b;
        const int4* src = reinterpret_cast<const int4*>(x + (size_t)row * KDIM) + tid * 4;
        int sum = 0;
        unsigned int packed[4];
        #pragma unroll
        for (int i = 0; i < 4; i++) {
            int4 v = src[i];
            sum += v.x + v.y + v.z + v.w;
            packed[i] = (v.x & 0xFF) | ((v.y & 0xFF) << 8) | ((v.z & 0xFF) << 16) | ((v.w & 0xFF) << 24);
        }
        uint4 o = make_uint4(packed[0], packed[1], packed[2], packed[3]);
        reinterpret_cast<uint4*>(g_xa + (size_t)row * KDIM)[tid] = o;

        #pragma unroll
        for (int s = 16; s > 0; s >>= 1) sum += __shfl_down_sync(0xFFFFFFFF, sum, s);
        __shared__ int warp_s[8];
        if ((tid & 31) == 0) warp_s[tid >> 5] = sum;
        __syncthreads();
        if (tid == 0) {
            int t = 0;
            #pragma unroll
            for (int w = 0; w < 8; w++) t += warp_s[w];
            g_rx[row] = t * 160;
        }
    } else {
        int t0 = b - MDIM;               // 0..4095
        int n0 = (t0 & 127) * 32;
        int k0 = (t0 >> 7) * 128;
        int tx = tid & 31;
        int ty = tid >> 5;
        __shared__ unsigned int sh32[32][33];
        __shared__ int red[8][32];
        unsigned char* shb = reinterpret_cast<unsigned char*>(sh32);
        int csum = 0;
        #pragma unroll
        for (int r = 0; r < 16; r++) {
            int kk = ty + r * 8;
            int v = y[(size_t)(k0 + kk) * NDIM + n0 + tx];
            csum += v;
            shb[tx * 132 + kk] = (unsigned char)v;
        }
        red[ty][tx] = csum;
        __syncthreads();
        int n = tid >> 3;
        int wq = tid & 7;
        uint4 o;
        o.x = sh32[n][wq * 4 + 0];
        o.y = sh32[n][wq * 4 + 1];
        o.z = sh32[n][wq * 4 + 2];
        o.w = sh32[n][wq * 4 + 3];
        *reinterpret_cast<uint4*>(&g_yb[(size_t)(n0 + n) * KDIM + k0 + wq * 16]) = o;
        if (ty == 0) {
            int s = 0;
            #pragma unroll
            for (int w = 0; w < 8; w++) s += red[w][tx];
            atomicAdd(&g_cy[n0 + tx], s);
        }
    }
}

// ---------------- GEMM: tensor (chunks 0..27) + dp4a on scalar pipe (last 512B of K) ----------------
static constexpr int BM = 128;
static constexpr int BN = 128;
static constexpr int BKB = 128;                  // k bytes per chunk
static constexpr int NCHUNK = 28;                // MMA covers k-bytes [0, 3584)
static constexpr int DP_K0 = NCHUNK * BKB;       // 3584: dp4a covers [3584, 4096) = 64 bites x 8B
static constexpr int STAGES = 3;
static constexpr int TILE_BYTES = BM * BKB;      // 16384 (A), same for B
static constexpr int STAGE_BYTES = 2 * TILE_BYTES;   // 32768
static constexpr int CORR_OFF = STAGES * STAGE_BYTES;        // 98304: sRX[128], sCY[128]
static constexpr int MBAR_OFF = CORR_OFF + 1024;
static constexpr int SMEM_TOTAL = MBAR_OFF + 64;             // 99392

__device__ __forceinline__ uint32_t smem_to_u32(const void* p) {
    uint32_t a;
    asm("{ .reg .u64 t; cvta.to.shared.u64 t, %1; cvt.u32.u64 %0, t; }" : "=r"(a) : "l"(p));
    return a;
}

#define LDSM_X4(r0, r1, r2, r3, addr) \
    asm volatile("ldmatrix.sync.aligned.m8n8.x4.shared.b16 {%0,%1,%2,%3}, [%4];" \
        : "=r"(r0), "=r"(r1), "=r"(r2), "=r"(r3) : "r"(addr))

#define MMA_S8U8(d, a, b0, b1) \
    asm volatile("mma.sync.aligned.m16n8k32.row.col.s32.s8.u8.s32 " \
        "{%0,%1,%2,%3}, {%4,%5,%6,%7}, {%8,%9}, {%0,%1,%2,%3};" \
        : "+r"((d)[0]), "+r"((d)[1]), "+r"((d)[2]), "+r"((d)[3]) \
        : "r"((a)[0]), "r"((a)[1]), "r"((a)[2]), "r"((a)[3]), "r"(b0), "r"(b1))

// a: s8x4 packed, b: u8x4 packed, acc += dot
#define DP4A(acc, a, b) \
    asm("dp4a.s32.u32 %0, %1, %2, %0;" : "+r"(acc) : "r"(a), "r"(b))

#define CP_ASYNC16(dst, src) \
    asm volatile("cp.async.cg.shared.global [%0], [%1], 16;\n" :: "r"(dst), "l"(src))

#define MBAR_INIT(addr, cnt) \
    asm volatile("mbarrier.init.shared.b64 [%0], %1;" :: "r"(addr), "r"(cnt) : "memory")
#define MBAR_ARRIVE(addr) \
    asm volatile("mbarrier.arrive.shared.b64 _, [%0];" :: "r"(addr) : "memory")
#define CP_MBAR_NOINC(addr) \
    asm volatile("cp.async.mbarrier.arrive.noinc.shared.b64 [%0];" :: "r"(addr) : "memory")
#define MBAR_WAIT(addr, parity) do { \
    uint32_t _m = (addr); uint32_t _p = (parity); uint32_t _ok; \
    asm volatile("{\n\t.reg .pred p;\n\t" \
        "mbarrier.try_wait.parity.acquire.cta.shared::cta.b64 p, [%1], %2;\n\t" \
        "selp.b32 %0, 1, 0, p;\n\t}" : "=r"(_ok) : "r"(_m), "r"(_p) : "memory"); \
    if (!_ok) { \
        asm volatile("{\n\t.reg .pred P1;\n\t" \
            "WL_%=:\n\t" \
            "mbarrier.try_wait.parity.acquire.cta.shared::cta.b64 P1, [%0], %1, 0x989680;\n\t" \
            "@P1 bra.uni WD_%=;\n\t" \
            "bra.uni WL_%=;\n\t" \
            "WD_%=:\n\t}" :: "r"(_m), "r"(_p) : "memory"); \
    } \
} while (0)

__global__ __launch_bounds__(256, 2) void gemm_s8_kernel(float* __restrict__ out) {
    extern __shared__ __align__(1024) char smem[];
    uint32_t sb = smem_to_u32(smem);
    int tid  = threadIdx.x;
    int wid  = tid >> 5;
    int lane = tid & 31;

    int m0 = blockIdx.y * BM;
    int n0 = blockIdx.x * BN;
    int wm = (wid >> 2) * 64;      // warp M offset
    int wn = (wid & 3) * 32;       // warp N offset

    const char* gA = reinterpret_cast<const char*>(g_xa) + (size_t)m0 * KDIM;
    const char* gB = reinterpret_cast<const char*>(g_yb) + (size_t)n0 * KDIM;

    uint32_t mb_full  = sb + MBAR_OFF;
    uint32_t mb_empty = sb + MBAR_OFF + 24;
    if (tid == 0) {
        #pragma unroll
        for (int s = 0; s < STAGES; s++) {
            MBAR_INIT(mb_full + 8 * s, 256);
            MBAR_INIT(mb_empty + 8 * s, 256);
        }
    }

    int* sRX = reinterpret_cast<int*>(smem + CORR_OFF);
    int* sCY = sRX + 128;
    if (tid < 128) {
        sRX[tid] = __ldg(&g_rx[m0 + tid]);
    } else {
        sCY[tid - 128] = __ldg(&g_cy[n0 + (tid - 128)]) * 66 + KZZ;
    }

    // cp.async dst offsets (smem, constant per thread); srcs recomputed per call
    uint32_t cp_dst[8];
    {
        #pragma unroll
        for (int i = 0; i < 8; i++) {
            int idx = tid + i * 256;
            int which = idx >> 10;
            int j = idx & 1023;
            uint32_t off = (uint32_t)((j >> 3) * BKB + (j & 7) * 16);
            cp_dst[i] = (uint32_t)(which * TILE_BYTES) + (off ^ ((off >> 3) & 0x70));
        }
    }

    // ldmatrix per-thread bases
    int rA = ((lane >> 3) & 1) * 8 + (lane & 7);
    int kA = ((lane >> 4) & 1) * 16;
    uint32_t offA_lin = (uint32_t)((wm + rA) * BKB + kA);
    int rB = ((lane >> 4) & 1) * 8 + (lane & 7);
    int kB = ((lane >> 3) & 1) * 16;
    uint32_t offB_lin = (uint32_t)((wn + rB) * BKB + kB);
    uint32_t xmA = (uint32_t)((rA & 7) << 4);
    uint32_t xmB = (uint32_t)((rB & 7) << 4);

    // dp4a ownership (matches MMA fragment layout)
    int rlo = lane >> 2;           // row within 8-row group
    int cc  = (lane & 3) * 2;      // even col within 8-col group

    int d[4][4][4];
    #pragma unroll
    for (int mi = 0; mi < 4; mi++)
        #pragma unroll
        for (int ni = 0; ni < 4; ni++)
            #pragma unroll
            for (int r = 0; r < 4; r++) d[mi][ni][r] = 0;

    auto load_chunk = [&](int c, int s) {
        uint32_t base = sb + (uint32_t)s * STAGE_BYTES;
        size_t koff = (size_t)c * BKB;
        #pragma unroll
        for (int i = 0; i < 8; i++) {
            int idx = tid + i * 256;
            int which = idx >> 10;
            int j = idx & 1023;
            const char* src = (which ? gB : gA) + (size_t)(j >> 3) * KDIM + (j & 7) * 16 + koff;
            CP_ASYNC16(base + cp_dst[i], src);
        }
        CP_MBAR_NOINC(mb_full + 8 * s);
    };

    // one 8-byte dp4a bite: accumulate k-bytes [DP_K0+8*bi, +8) into d
    auto dp_bite = [&](int bi) {
        int kb = DP_K0 + bi * 8;
        // hoist B: 8 cols (4 ni pairs)
        uint2 bw[8];
        #pragma unroll
        for (int ni = 0; ni < 4; ni++) {
            const char* pb = gB + (size_t)(wn + ni * 8 + cc) * KDIM + kb;
            bw[2 * ni]     = *reinterpret_cast<const uint2*>(pb);
            bw[2 * ni + 1] = *reinterpret_cast<const uint2*>(pb + KDIM);
        }
        #pragma unroll
        for (int mi = 0; mi < 4; mi++) {
            const char* pa = gA + (size_t)(wm + mi * 16 + rlo) * KDIM + kb;
            uint2 a0 = *reinterpret_cast<const uint2*>(pa);
            uint2 a1 = *reinterpret_cast<const uint2*>(pa + 8 * KDIM);
            #pragma unroll
            for (int ni = 0; ni < 4; ni++) {
                DP4A(d[mi][ni][0], a0.x, bw[2 * ni].x);     DP4A(d[mi][ni][0], a0.y, bw[2 * ni].y);
                DP4A(d[mi][ni][1], a0.x, bw[2 * ni + 1].x); DP4A(d[mi][ni][1], a0.y, bw[2 * ni + 1].y);
                DP4A(d[mi][ni][2], a1.x, bw[2 * ni].x);     DP4A(d[mi][ni][2], a1.y, bw[2 * ni].y);
                DP4A(d[mi][ni][3], a1.x, bw[2 * ni + 1].x); DP4A(d[mi][ni][3], a1.y, bw[2 * ni + 1].y);
            }
        }
    };

    __syncthreads();   // mbarrier init + sRX/sCY visible

    load_chunk(0, 0);
    load_chunk(1, 1);

    int cs = 0, cpar = 0;
    int ps = 2;
    int ppar = 1;
    int bi = 0;        // dp4a bite counter (0..63)

    #pragma unroll 1
    for (int c = 0; c < NCHUNK; c++) {
        MBAR_WAIT(mb_full + 8 * cs, cpar);

        uint32_t stA = sb + (uint32_t)cs * STAGE_BYTES;
        uint32_t stB = stA + TILE_BYTES;

        #pragma unroll
        for (int ks = 0; ks < 4; ks++) {
            uint32_t a[4][4];
            #pragma unroll
            for (int mi = 0; mi < 4; mi++) {
                uint32_t addr = stA + ((offA_lin + (uint32_t)(mi * 2048 + ks * 32)) ^ xmA);
                LDSM_X4(a[mi][0], a[mi][1], a[mi][2], a[mi][3], addr);
            }
            uint32_t b[4][2];
            #pragma unroll
            for (int j2 = 0; j2 < 2; j2++) {
                uint32_t addr = stB + ((offB_lin + (uint32_t)(j2 * 2048 + ks * 32)) ^ xmB);
                LDSM_X4(b[2 * j2][0], b[2 * j2][1], b[2 * j2 + 1][0], b[2 * j2 + 1][1], addr);
            }
            #pragma unroll
            for (int mi = 0; mi < 4; mi++)
                #pragma unroll
                for (int ni = 0; ni < 4; ni++)
                    MMA_S8U8(d[mi][ni], a[mi], b[ni][0], b[ni][1]);
        }

        MBAR_ARRIVE(mb_empty + 8 * cs);

        // dp4a side-channel work on the scalar pipe: 3 bites for c<8, else 2 (8*3+20*2=64)
        {
            int nb = (c < 8) ? 3 : 2;
            #pragma unroll 1
            for (int q = 0; q < nb; q++) { dp_bite(bi); bi++; }
        }

        // prefetch chunk c+2
        int t = c + 2;
        if (t < NCHUNK) {
            if (ps == 0) ppar ^= 1;
            if (t >= STAGES) MBAR_WAIT(mb_empty + 8 * ps, ppar);
            load_chunk(t, ps);
            ps = (ps == 2) ? 0 : ps + 1;
        }

        cs = (cs == 2) ? 0 : cs + 1;
        if (cs == 0) cpar ^= 1;
    }

    // ---------------- epilogue: zero-point correction + scale (smem-fed) ----------------
    const float S = OUT_SCALE;
    #pragma unroll
    for (int mi = 0; mi < 4; mi++) {
        int lrow = wm + mi * 16 + rlo;
        int row0 = m0 + lrow;
        int rxa = sRX[lrow];
        int rxb = sRX[lrow + 8];
        #pragma unroll
        for (int ni = 0; ni < 4; ni++) {
            int lcol = wn + ni * 8 + cc;
            int col = n0 + lcol;
            int cy0 = sCY[lcol];
            int cy1 = sCY[lcol + 1];
            const int* dd = d[mi][ni];
            float2 v0, v1;
            v0.x = S * (float)(dd[0] - rxa + cy0);
            v0.y = S * (float)(dd[1] - rxa + cy1);
            v1.x = S * (float)(dd[2] - rxb + cy0);
            v1.y = S * (float)(dd[3] - rxb + cy1);
            *reinterpret_cast<float2*>(out + (size_t)row0 * NDIM + col) = v0;
            *reinterpret_cast<float2*>(out + (size_t)(row0 + 8) * NDIM + col) = v1;
        }
    }
}

// ---------------- launch ----------------
extern "C" void kernel_launch(void* const* d_in, const int* in_sizes, int n_in,
                              void* d_out, int out_size) {
    const int* x = (const int*)d_in[0];   // [M, K] int32 (int8-range)
    const int* y = (const int*)d_in[1];   // [K, N] int32 (uint8-range)
    float* out = (float*)d_out;

    void* cy_ptr = nullptr;
    cudaGetSymbolAddress(&cy_ptr, g_cy);
    cudaMemsetAsync(cy_ptr, 0, NDIM * sizeof(int), 0);

    conv_kernel<<<MDIM + 4096, 256>>>(x, y);

    cudaFuncSetAttribute(gemm_s8_kernel, cudaFuncAttributeMaxDynamicSharedMemorySize, SMEM_TOTAL);
    gemm_s8_kernel<<<dim3(NDIM / BN, MDIM / BM), 256, SMEM_TOTAL>>>(out);
}

// round 16
// speedup vs baseline: 1.7839x; 1.0139x over previous
#include <cuda_runtime.h>
#include <cuda_bf16.h>
#include <cstdint>

// ---------------- problem constants ----------------
#define MDIM 4096
#define NDIM 4096
#define KDIM 4096
#define KZZ (-43253760)          // 4096 * (-66) * 160
#define OUT_SCALE (0.03f * 0.025f)

// ---------------- scratch ----------------
__device__ unsigned char g_xa[(size_t)MDIM * KDIM];   // x packed s8, row-major [M,K]
__device__ unsigned char g_yb[(size_t)NDIM * KDIM];   // y packed u8, K-major [N,K]
__device__ int g_rx[MDIM];                            // rowsum of x, premultiplied by 160
__device__ int g_cy[NDIM];                            // colsum of y

// ---------------- merged conversion kernel (proven config) ----------------
__global__ __launch_bounds__(256) void conv_kernel(const int* __restrict__ x,
                                                   const int* __restrict__ y) {
    int b = blockIdx.x;
    int tid = threadIdx.x;
    if (b < MDIM) {
        int row = b;
        const int4* src = reinterpret_cast<const int4*>(x + (size_t)row * KDIM) + tid * 4;
        int sum = 0;
        unsigned int packed[4];
        #pragma unroll
        for (int i = 0; i < 4; i++) {
            int4 v = src[i];
            sum += v.x + v.y + v.z + v.w;
            packed[i] = (v.x & 0xFF) | ((v.y & 0xFF) << 8) | ((v.z & 0xFF) << 16) | ((v.w & 0xFF) << 24);
        }
        uint4 o = make_uint4(packed[0], packed[1], packed[2], packed[3]);
        reinterpret_cast<uint4*>(g_xa + (size_t)row * KDIM)[tid] = o;

        #pragma unroll
        for (int s = 16; s > 0; s >>= 1) sum += __shfl_down_sync(0xFFFFFFFF, sum, s);
        __shared__ int warp_s[8];
        if ((tid & 31) == 0) warp_s[tid >> 5] = sum;
        __syncthreads();
        if (tid == 0) {
            int t = 0;
            #pragma unroll
            for (int w = 0; w < 8; w++) t += warp_s[w];
            g_rx[row] = t * 160;
        }
    } else {
        int t0 = b - MDIM;               // 0..4095
        int n0 = (t0 & 127) * 32;
        int k0 = (t0 >> 7) * 128;
        int tx = tid & 31;
        int ty = tid >> 5;
        __shared__ unsigned int sh32[32][33];
        __shared__ int red[8][32];
        unsigned char* shb = reinterpret_cast<unsigned char*>(sh32);
        int csum = 0;
        #pragma unroll
        for (int r = 0; r < 16; r++) {
            int kk = ty + r * 8;
            int v = y[(size_t)(k0 + kk) * NDIM + n0 + tx];
            csum += v;
            shb[tx * 132 + kk] = (unsigned char)v;
        }
        red[ty][tx] = csum;
        __syncthreads();
        int n = tid >> 3;
        int wq = tid & 7;
        uint4 o;
        o.x = sh32[n][wq * 4 + 0];
        o.y = sh32[n][wq * 4 + 1];
        o.z = sh32[n][wq * 4 + 2];
        o.w = sh32[n][wq * 4 + 3];
        *reinterpret_cast<uint4*>(&g_yb[(size_t)(n0 + n) * KDIM + k0 + wq * 16]) = o;
        if (ty == 0) {
            int s = 0;
            #pragma unroll
            for (int w = 0; w < 8; w++) s += red[w][tx];
            atomicAdd(&g_cy[n0 + tx], s);
        }
    }
}

// ---------------- GEMM: tensor (chunks 0..23) + dp4a on scalar pipe (last 1024B of K) ----------------
static constexpr int BM = 128;
static constexpr int BN = 128;
static constexpr int BKB = 128;                  // k bytes per chunk
static constexpr int NCHUNK = 24;                // MMA covers k-bytes [0, 3072)
static constexpr int DP_K0 = NCHUNK * BKB;       // 3072: dp4a covers [3072, 4096) = 128 bites x 8B
static constexpr int STAGES = 3;
static constexpr int TILE_BYTES = BM * BKB;      // 16384 (A), same for B
static constexpr int STAGE_BYTES = 2 * TILE_BYTES;   // 32768
static constexpr int CORR_OFF = STAGES * STAGE_BYTES;        // 98304: sRX[128], sCY[128]
static constexpr int MBAR_OFF = CORR_OFF + 1024;
static constexpr int SMEM_TOTAL = MBAR_OFF + 64;             // 99392

__device__ __forceinline__ uint32_t smem_to_u32(const void* p) {
    uint32_t a;
    asm("{ .reg .u64 t; cvta.to.shared.u64 t, %1; cvt.u32.u64 %0, t; }" : "=r"(a) : "l"(p));
    return a;
}

#define LDSM_X4(r0, r1, r2, r3, addr) \
    asm volatile("ldmatrix.sync.aligned.m8n8.x4.shared.b16 {%0,%1,%2,%3}, [%4];" \
        : "=r"(r0), "=r"(r1), "=r"(r2), "=r"(r3) : "r"(addr))

#define MMA_S8U8(d, a, b0, b1) \
    asm volatile("mma.sync.aligned.m16n8k32.row.col.s32.s8.u8.s32 " \
        "{%0,%1,%2,%3}, {%4,%5,%6,%7}, {%8,%9}, {%0,%1,%2,%3};" \
        : "+r"((d)[0]), "+r"((d)[1]), "+r"((d)[2]), "+r"((d)[3]) \
        : "r"((a)[0]), "r"((a)[1]), "r"((a)[2]), "r"((a)[3]), "r"(b0), "r"(b1))

// a: s8x4 packed, b: u8x4 packed, acc += dot
#define DP4A(acc, a, b) \
    asm("dp4a.s32.u32 %0, %1, %2, %0;" : "+r"(acc) : "r"(a), "r"(b))

#define CP_ASYNC16(dst, src) \
    asm volatile("cp.async.cg.shared.global [%0], [%1], 16;\n" :: "r"(dst), "l"(src))

#define MBAR_INIT(addr, cnt) \
    asm volatile("mbarrier.init.shared.b64 [%0], %1;" :: "r"(addr), "r"(cnt) : "memory")
#define MBAR_ARRIVE(addr) \
    asm volatile("mbarrier.arrive.shared.b64 _, [%0];" :: "r"(addr) : "memory")
#define CP_MBAR_NOINC(addr) \
    asm volatile("cp.async.mbarrier.arrive.noinc.shared.b64 [%0];" :: "r"(addr) : "memory")
#define MBAR_WAIT(addr, parity) do { \
    uint32_t _m = (addr); uint32_t _p = (parity); uint32_t _ok; \
    asm volatile("{\n\t.reg .pred p;\n\t" \
        "mbarrier.try_wait.parity.acquire.cta.shared::cta.b64 p, [%1], %2;\n\t" \
        "selp.b32 %0, 1, 0, p;\n\t}" : "=r"(_ok) : "r"(_m), "r"(_p) : "memory"); \
    if (!_ok) { \
        asm volatile("{\n\t.reg .pred P1;\n\t" \
            "WL_%=:\n\t" \
            "mbarrier.try_wait.parity.acquire.cta.shared::cta.b64 P1, [%0], %1, 0x989680;\n\t" \
            "@P1 bra.uni WD_%=;\n\t" \
            "bra.uni WL_%=;\n\t" \
            "WD_%=:\n\t}" :: "r"(_m), "r"(_p) : "memory"); \
    } \
} while (0)

__global__ __launch_bounds__(256, 2) void gemm_s8_kernel(float* __restrict__ out) {
    extern __shared__ __align__(1024) char smem[];
    uint32_t sb = smem_to_u32(smem);
    int tid  = threadIdx.x;
    int wid  = tid >> 5;
    int lane = tid & 31;

    int m0 = blockIdx.y * BM;
    int n0 = blockIdx.x * BN;
    int wm = (wid >> 2) * 64;      // warp M offset
    int wn = (wid & 3) * 32;       // warp N offset

    const char* gA = reinterpret_cast<const char*>(g_xa) + (size_t)m0 * KDIM;
    const char* gB = reinterpret_cast<const char*>(g_yb) + (size_t)n0 * KDIM;

    uint32_t mb_full  = sb + MBAR_OFF;
    uint32_t mb_empty = sb + MBAR_OFF + 24;
    if (tid == 0) {
        #pragma unroll
        for (int s = 0; s < STAGES; s++) {
            MBAR_INIT(mb_full + 8 * s, 256);
            MBAR_INIT(mb_empty + 8 * s, 256);
        }
    }

    int* sRX = reinterpret_cast<int*>(smem + CORR_OFF);
    int* sCY = sRX + 128;
    if (tid < 128) {
        sRX[tid] = __ldg(&g_rx[m0 + tid]);
    } else {
        sCY[tid - 128] = __ldg(&g_cy[n0 + (tid - 128)]) * 66 + KZZ;
    }

    // cp.async dst offsets (smem, constant per thread); srcs recomputed per call
    uint32_t cp_dst[8];
    {
        #pragma unroll
        for (int i = 0; i < 8; i++) {
            int idx = tid + i * 256;
            int which = idx >> 10;
            int j = idx & 1023;
            uint32_t off = (uint32_t)((j >> 3) * BKB + (j & 7) * 16);
            cp_dst[i] = (uint32_t)(which * TILE_BYTES) + (off ^ ((off >> 3) & 0x70));
        }
    }

    // ldmatrix per-thread bases
    int rA = ((lane >> 3) & 1) * 8 + (lane & 7);
    int kA = ((lane >> 4) & 1) * 16;
    uint32_t offA_lin = (uint32_t)((wm + rA) * BKB + kA);
    int rB = ((lane >> 4) & 1) * 8 + (lane & 7);
    int kB = ((lane >> 3) & 1) * 16;
    uint32_t offB_lin = (uint32_t)((wn + rB) * BKB + kB);
    uint32_t xmA = (uint32_t)((rA & 7) << 4);
    uint32_t xmB = (uint32_t)((rB & 7) << 4);

    // dp4a ownership (matches MMA fragment layout)
    int rlo = lane >> 2;           // row within 8-row group
    int cc  = (lane & 3) * 2;      // even col within 8-col group

    int d[4][4][4];
    #pragma unroll
    for (int mi = 0; mi < 4; mi++)
        #pragma unroll
        for (int ni = 0; ni < 4; ni++)
            #pragma unroll
            for (int r = 0; r < 4; r++) d[mi][ni][r] = 0;

    auto load_chunk = [&](int c, int s) {
        uint32_t base = sb + (uint32_t)s * STAGE_BYTES;
        size_t koff = (size_t)c * BKB;
        #pragma unroll
        for (int i = 0; i < 8; i++) {
            int idx = tid + i * 256;
            int which = idx >> 10;
            int j = idx & 1023;
            const char* src = (which ? gB : gA) + (size_t)(j >> 3) * KDIM + (j & 7) * 16 + koff;
            CP_ASYNC16(base + cp_dst[i], src);
        }
        CP_MBAR_NOINC(mb_full + 8 * s);
    };

    // one 8-byte dp4a bite: accumulate k-bytes [DP_K0+8*bi, +8) into d
    auto dp_bite = [&](int bi) {
        int kb = DP_K0 + bi * 8;
        uint2 bw[8];
        #pragma unroll
        for (int ni = 0; ni < 4; ni++) {
            const char* pb = gB + (size_t)(wn + ni * 8 + cc) * KDIM + kb;
            bw[2 * ni]     = *reinterpret_cast<const uint2*>(pb);
            bw[2 * ni + 1] = *reinterpret_cast<const uint2*>(pb + KDIM);
        }
        #pragma unroll
        for (int mi = 0; mi < 4; mi++) {
            const char* pa = gA + (size_t)(wm + mi * 16 + rlo) * KDIM + kb;
            uint2 a0 = *reinterpret_cast<const uint2*>(pa);
            uint2 a1 = *reinterpret_cast<const uint2*>(pa + 8 * KDIM);
            #pragma unroll
            for (int ni = 0; ni < 4; ni++) {
                DP4A(d[mi][ni][0], a0.x, bw[2 * ni].x);     DP4A(d[mi][ni][0], a0.y, bw[2 * ni].y);
                DP4A(d[mi][ni][1], a0.x, bw[2 * ni + 1].x); DP4A(d[mi][ni][1], a0.y, bw[2 * ni + 1].y);
                DP4A(d[mi][ni][2], a1.x, bw[2 * ni].x);     DP4A(d[mi][ni][2], a1.y, bw[2 * ni].y);
                DP4A(d[mi][ni][3], a1.x, bw[2 * ni + 1].x); DP4A(d[mi][ni][3], a1.y, bw[2 * ni + 1].y);
            }
        }
    };

    __syncthreads();   // mbarrier init + sRX/sCY visible

    load_chunk(0, 0);
    load_chunk(1, 1);

    int cs = 0, cpar = 0;
    int ps = 2;
    int ppar = 1;
    int bi = 0;        // dp4a bite counter (0..127)

    #pragma unroll 1
    for (int c = 0; c < NCHUNK; c++) {
        MBAR_WAIT(mb_full + 8 * cs, cpar);

        uint32_t stA = sb + (uint32_t)cs * STAGE_BYTES;
        uint32_t stB = stA + TILE_BYTES;

        #pragma unroll
        for (int ks = 0; ks < 4; ks++) {
            uint32_t a[4][4];
            #pragma unroll
            for (int mi = 0; mi < 4; mi++) {
                uint32_t addr = stA + ((offA_lin + (uint32_t)(mi * 2048 + ks * 32)) ^ xmA);
                LDSM_X4(a[mi][0], a[mi][1], a[mi][2], a[mi][3], addr);
            }
            uint32_t b[4][2];
            #pragma unroll
            for (int j2 = 0; j2 < 2; j2++) {
                uint32_t addr = stB + ((offB_lin + (uint32_t)(j2 * 2048 + ks * 32)) ^ xmB);
                LDSM_X4(b[2 * j2][0], b[2 * j2][1], b[2 * j2 + 1][0], b[2 * j2 + 1][1], addr);
            }
            #pragma unroll
            for (int mi = 0; mi < 4; mi++)
                #pragma unroll
                for (int ni = 0; ni < 4; ni++)
                    MMA_S8U8(d[mi][ni], a[mi], b[ni][0], b[ni][1]);
        }

        MBAR_ARRIVE(mb_empty + 8 * cs);

        // dp4a side-channel work: 6 bites for c<8, else 5 (8*6 + 16*5 = 128)
        {
            int nb = (c < 8) ? 6 : 5;
            #pragma unroll 1
            for (int q = 0; q < nb; q++) { dp_bite(bi); bi++; }
        }

        // prefetch chunk c+2
        int t = c + 2;
        if (t < NCHUNK) {
            if (ps == 0) ppar ^= 1;
            if (t >= STAGES) MBAR_WAIT(mb_empty + 8 * ps, ppar);
            load_chunk(t, ps);
            ps = (ps == 2) ? 0 : ps + 1;
        }

        cs = (cs == 2) ? 0 : cs + 1;
        if (cs == 0) cpar ^= 1;
    }

    // ---------------- epilogue: zero-point correction + scale (smem-fed) ----------------
    const float S = OUT_SCALE;
    #pragma unroll
    for (int mi = 0; mi < 4; mi++) {
        int lrow = wm + mi * 16 + rlo;
        int row0 = m0 + lrow;
        int rxa = sRX[lrow];
        int rxb = sRX[lrow + 8];
        #pragma unroll
        for (int ni = 0; ni < 4; ni++) {
            int lcol = wn + ni * 8 + cc;
            int col = n0 + lcol;
            int cy0 = sCY[lcol];
            int cy1 = sCY[lcol + 1];
            const int* dd = d[mi][ni];
            float2 v0, v1;
            v0.x = S * (float)(dd[0] - rxa + cy0);
            v0.y = S * (float)(dd[1] - rxa + cy1);
            v1.x = S * (float)(dd[2] - rxb + cy0);
            v1.y = S * (float)(dd[3] - rxb + cy1);
            *reinterpret_cast<float2*>(out + (size_t)row0 * NDIM + col) = v0;
            *reinterpret_cast<float2*>(out + (size_t)(row0 + 8) * NDIM + col) = v1;
        }
    }
}

// ---------------- launch ----------------
extern "C" void kernel_launch(void* const* d_in, const int* in_sizes, int n_in,
                              void* d_out, int out_size) {
    const int* x = (const int*)d_in[0];   // [M, K] int32 (int8-range)
    const int* y = (const int*)d_in[1];   // [K, N] int32 (uint8-range)
    float* out = (float*)d_out;

    void* cy_ptr = nullptr;
    cudaGetSymbolAddress(&cy_ptr, g_cy);
    cudaMemsetAsync(cy_ptr, 0, NDIM * sizeof(int), 0);

    conv_kernel<<<MDIM + 4096, 256>>>(x, y);

    cudaFuncSetAttribute(gemm_s8_kernel, cudaFuncAttributeMaxDynamicSharedMemorySize, SMEM_TOTAL);
    gemm_s8_kernel<<<dim3(NDIM / BN, MDIM / BM), 256, SMEM_TOTAL>>>(out);
}